// round 1
// baseline (speedup 1.0000x reference)
#include <cuda_runtime.h>

#define NN 50000
#define NE 1600000
#define NEG 0.2f

// ---------------- scratch (device globals; no allocation allowed) ----------
__device__ float4 g_hq[NN];          // per-node h_q (4 heads)
__device__ float4 g_kact[NN];        // per-node leaky(x@Wk^T)
__device__ float4 g_qagg[NN];        // per-node aggregated q
__device__ float4 g_hproj[NN * 32];  // per-node x@Wl^T + bl (128 f32 = 32 float4)
__device__ int    g_deg[NN];
__device__ int    g_rowptr[NN + 1];
__device__ int    g_pos[NN];
__device__ int    g_ccol[NE];        // CSR: col indices sorted by row

// ---------------- CSR build ----------------
__global__ void kzero() {
    int i = blockIdx.x * blockDim.x + threadIdx.x;
    if (i < NN) g_deg[i] = 0;
}

__global__ void khist(const int* __restrict__ ei) {
    int e = blockIdx.x * blockDim.x + threadIdx.x;
    if (e < NE) atomicAdd(&g_deg[ei[e]], 1);
}

__global__ void kscan() {
    __shared__ int sums[1024];
    const int T = 1024;
    const int ITEMS = (NN + T - 1) / T;  // 49
    int t = threadIdx.x;
    int start = t * ITEMS;
    int end = min(start + ITEMS, NN);
    int s = 0;
    for (int i = start; i < end; i++) s += g_deg[i];
    sums[t] = s;
    __syncthreads();
    for (int off = 1; off < T; off <<= 1) {
        int v = (t >= off) ? sums[t - off] : 0;
        __syncthreads();
        sums[t] += v;
        __syncthreads();
    }
    int prefix = (t == 0) ? 0 : sums[t - 1];
    for (int i = start; i < end; i++) {
        g_rowptr[i] = prefix;
        g_pos[i] = prefix;
        prefix += g_deg[i];
    }
    if (t == T - 1) g_rowptr[NN] = prefix;
}

__global__ void kscatter(const int* __restrict__ ei) {
    int e = blockIdx.x * blockDim.x + threadIdx.x;
    if (e < NE) {
        int r = ei[e];
        int p = atomicAdd(&g_pos[r], 1);
        g_ccol[p] = ei[NE + e];
    }
}

// ---------------- per-node small projections: h_q, k_act -------------------
__global__ void kprojsmall(const float* __restrict__ x,
                           const float* __restrict__ Wq,
                           const float* __restrict__ Wk) {
    int w = (blockIdx.x * blockDim.x + threadIdx.x) >> 5;
    int lane = threadIdx.x & 31;
    if (w >= NN) return;
    float4 xv = ((const float4*)x)[w * 32 + lane];
    float a[8];
#pragma unroll
    for (int h = 0; h < 4; h++) {
        float4 q = ((const float4*)Wq)[h * 32 + lane];
        float4 k = ((const float4*)Wk)[h * 32 + lane];
        a[h]     = xv.x * q.x + xv.y * q.y + xv.z * q.z + xv.w * q.w;
        a[4 + h] = xv.x * k.x + xv.y * k.y + xv.z * k.z + xv.w * k.w;
    }
#pragma unroll
    for (int off = 16; off; off >>= 1) {
#pragma unroll
        for (int h = 0; h < 8; h++) a[h] += __shfl_xor_sync(0xffffffffu, a[h], off);
    }
    if (lane == 0) {
        g_hq[w] = make_float4(a[0], a[1], a[2], a[3]);
        float4 kk;
        kk.x = a[4] >= 0.f ? a[4] : NEG * a[4];
        kk.y = a[5] >= 0.f ? a[5] : NEG * a[5];
        kk.z = a[6] >= 0.f ? a[6] : NEG * a[6];
        kk.w = a[7] >= 0.f ? a[7] : NEG * a[7];
        g_kact[w] = kk;
    }
}

// ---------------- h_proj GEMM: [NN,128] = x[NN,128] @ Wl^T[128,128] + bl ---
// 64 nodes x 64 outs per block, K chunked by 64, 256 threads, 4x4 reg tile.
__global__ __launch_bounds__(256) void kgemm(const float* __restrict__ x,
                                             const float* __restrict__ Wl,
                                             const float* __restrict__ bl) {
    __shared__ float xs[64 * 65];
    __shared__ float ws[64 * 65];
    int nb = blockIdx.x * 64;
    int ob = blockIdx.y * 64;
    int tid = threadIdx.x;
    int tx = tid & 15;   // outs:  o = tx + 16*oo
    int ty = tid >> 4;   // nodes: n = ty*4 + nn
    float acc[4][4];
#pragma unroll
    for (int a = 0; a < 4; a++)
#pragma unroll
        for (int b = 0; b < 4; b++) acc[a][b] = 0.f;

    for (int kb = 0; kb < 128; kb += 64) {
        // stage 64x64 tiles (1024 float4 each)
        for (int idx = tid; idx < 64 * 16; idx += 256) {
            int row = idx >> 4, c = idx & 15;
            float4 v = make_float4(0.f, 0.f, 0.f, 0.f);
            if (nb + row < NN) v = ((const float4*)x)[(nb + row) * 32 + (kb >> 2) + c];
            xs[row * 65 + c * 4 + 0] = v.x;
            xs[row * 65 + c * 4 + 1] = v.y;
            xs[row * 65 + c * 4 + 2] = v.z;
            xs[row * 65 + c * 4 + 3] = v.w;
            float4 wv = ((const float4*)Wl)[(ob + row) * 32 + (kb >> 2) + c];
            ws[row * 65 + c * 4 + 0] = wv.x;
            ws[row * 65 + c * 4 + 1] = wv.y;
            ws[row * 65 + c * 4 + 2] = wv.z;
            ws[row * 65 + c * 4 + 3] = wv.w;
        }
        __syncthreads();
#pragma unroll 4
        for (int k = 0; k < 64; k++) {
            float xr[4], wr[4];
#pragma unroll
            for (int nn = 0; nn < 4; nn++) xr[nn] = xs[(ty * 4 + nn) * 65 + k];
#pragma unroll
            for (int oo = 0; oo < 4; oo++) wr[oo] = ws[(tx + 16 * oo) * 65 + k];
#pragma unroll
            for (int nn = 0; nn < 4; nn++)
#pragma unroll
                for (int oo = 0; oo < 4; oo++) acc[nn][oo] = fmaf(xr[nn], wr[oo], acc[nn][oo]);
        }
        __syncthreads();
    }
    float* hp = (float*)g_hproj;
#pragma unroll
    for (int nn = 0; nn < 4; nn++) {
        int n = nb + ty * 4 + nn;
        if (n >= NN) continue;
#pragma unroll
        for (int oo = 0; oo < 4; oo++) {
            int o = ob + tx + 16 * oo;
            hp[n * 128 + o] = acc[nn][oo] + __ldg(&bl[o]);
        }
    }
}

// ---------------- q_agg: per-node sum of h_q over incoming edges -----------
__global__ void kqagg() {
    int i = (blockIdx.x * blockDim.x + threadIdx.x) >> 5;
    int lane = threadIdx.x & 31;
    if (i >= NN) return;
    int beg = g_rowptr[i], end = g_rowptr[i + 1];
    float4 a = make_float4(0.f, 0.f, 0.f, 0.f);
    for (int j = beg + lane; j < end; j += 32) {
        float4 q = g_hq[g_ccol[j]];
        a.x += q.x; a.y += q.y; a.z += q.z; a.w += q.w;
    }
#pragma unroll
    for (int off = 16; off; off >>= 1) {
        a.x += __shfl_xor_sync(0xffffffffu, a.x, off);
        a.y += __shfl_xor_sync(0xffffffffu, a.y, off);
        a.z += __shfl_xor_sync(0xffffffffu, a.z, off);
        a.w += __shfl_xor_sync(0xffffffffu, a.w, off);
    }
    if (lane == 0) g_qagg[i] = a;
}

// ---------------- fused softmax + aggregation + leaky ----------------------
__global__ __launch_bounds__(256) void kmain(float* __restrict__ out) {
    int i = (blockIdx.x * blockDim.x + threadIdx.x) >> 5;
    int lane = threadIdx.x & 31;
    if (i >= NN) return;
    int beg = g_rowptr[i], end = g_rowptr[i + 1];
    float4 k = g_kact[i];

    // pass 1: segment max per head
    float m0 = -1e30f, m1 = -1e30f, m2 = -1e30f, m3 = -1e30f;
    for (int j = beg + lane; j < end; j += 32) {
        float4 q = g_qagg[g_ccol[j]];
        m0 = fmaxf(m0, k.x * q.x);
        m1 = fmaxf(m1, k.y * q.y);
        m2 = fmaxf(m2, k.z * q.z);
        m3 = fmaxf(m3, k.w * q.w);
    }
#pragma unroll
    for (int off = 16; off; off >>= 1) {
        m0 = fmaxf(m0, __shfl_xor_sync(0xffffffffu, m0, off));
        m1 = fmaxf(m1, __shfl_xor_sync(0xffffffffu, m1, off));
        m2 = fmaxf(m2, __shfl_xor_sync(0xffffffffu, m2, off));
        m3 = fmaxf(m3, __shfl_xor_sync(0xffffffffu, m3, off));
    }

    // pass 2: sum of exp
    float s0 = 0.f, s1 = 0.f, s2 = 0.f, s3 = 0.f;
    for (int j = beg + lane; j < end; j += 32) {
        float4 q = g_qagg[g_ccol[j]];
        s0 += __expf(k.x * q.x - m0);
        s1 += __expf(k.y * q.y - m1);
        s2 += __expf(k.z * q.z - m2);
        s3 += __expf(k.w * q.w - m3);
    }
#pragma unroll
    for (int off = 16; off; off >>= 1) {
        s0 += __shfl_xor_sync(0xffffffffu, s0, off);
        s1 += __shfl_xor_sync(0xffffffffu, s1, off);
        s2 += __shfl_xor_sync(0xffffffffu, s2, off);
        s3 += __shfl_xor_sync(0xffffffffu, s3, off);
    }
    float i0 = 1.f / (s0 + 1e-8f);
    float i1 = 1.f / (s1 + 1e-8f);
    float i2 = 1.f / (s2 + 1e-8f);
    float i3 = 1.f / (s3 + 1e-8f);

    // pass 3: weighted aggregation of h_proj[col]
    float4 acc = make_float4(0.f, 0.f, 0.f, 0.f);
    for (int base = beg; base < end; base += 32) {
        int j = base + lane;
        int c = 0;
        float w = 0.f;
        if (j < end) {
            c = g_ccol[j];
            float4 q = g_qagg[c];
            w = 0.25f * (__expf(k.x * q.x - m0) * i0 +
                         __expf(k.y * q.y - m1) * i1 +
                         __expf(k.z * q.z - m2) * i2 +
                         __expf(k.w * q.w - m3) * i3);
        }
        int cnt = min(32, end - base);
        for (int jj = 0; jj < cnt; jj++) {
            int cc = __shfl_sync(0xffffffffu, c, jj);
            float ww = __shfl_sync(0xffffffffu, w, jj);
            float4 hp = g_hproj[cc * 32 + lane];
            acc.x = fmaf(ww, hp.x, acc.x);
            acc.y = fmaf(ww, hp.y, acc.y);
            acc.z = fmaf(ww, hp.z, acc.z);
            acc.w = fmaf(ww, hp.w, acc.w);
        }
    }
    float4 o;
    o.x = acc.x >= 0.f ? acc.x : NEG * acc.x;
    o.y = acc.y >= 0.f ? acc.y : NEG * acc.y;
    o.z = acc.z >= 0.f ? acc.z : NEG * acc.z;
    o.w = acc.w >= 0.f ? acc.w : NEG * acc.w;
    ((float4*)out)[i * 32 + lane] = o;
}

// ---------------- launch ----------------
extern "C" void kernel_launch(void* const* d_in, const int* in_sizes, int n_in,
                              void* d_out, int out_size) {
    const float* x  = (const float*)d_in[0];
    const int*   ei = (const int*)d_in[1];
    const float* Wq = (const float*)d_in[2];
    const float* Wk = (const float*)d_in[3];
    const float* Wl = (const float*)d_in[4];
    const float* bl = (const float*)d_in[5];
    float* out = (float*)d_out;

    kzero<<<(NN + 255) / 256, 256>>>();
    khist<<<(NE + 255) / 256, 256>>>(ei);
    kscan<<<1, 1024>>>();
    kscatter<<<(NE + 255) / 256, 256>>>(ei);
    kprojsmall<<<(NN * 32 + 255) / 256, 256>>>(x, Wq, Wk);
    kgemm<<<dim3((NN + 63) / 64, 2), 256>>>(x, Wl, bl);
    kqagg<<<(NN * 32 + 255) / 256, 256>>>();
    kmain<<<(NN * 32 + 255) / 256, 256>>>(out);
}